// round 11
// baseline (speedup 1.0000x reference)
#include <cuda_runtime.h>
#include <cuda_fp16.h>
#include <math.h>
#include <stdint.h>

#define SZ     4096
#define SEN    128
#define DC     128
#define OUTD   984
#define CCONST 160
#define GS     8
#define KT     21             // k16 steps = 3 taps * 7
#define VROWB  240            // bytes per v-tile row: 120 halves (112 data + 8 pad)
#define VH_BYTES (130 * VROWB)   // 31200 per sample tile (rows x = 0..129)

// SMEM byte offsets
#define SMB_B    0                      // 21*8*32 uint4 = 86016
#define SMB_VH   86016                  // 4 tiles * 31200 = 124800 -> 210816
#define SMB_MASK 210816                 // 2 bufs * 2 sm * 384 bytes = 1536 -> 212352
#define SMB_CB   212352                 // 2 bufs * 2 sm * 3*128 f = 6144 -> 218496
#define SMB_R    218496                 // 2*384*4 f = 12288 -> 230784
#define SMB_TOT  230784

typedef unsigned long long u64;

__device__ __align__(16) uint32_t gBfh[KT * 8 * 32 * 4];   // fp16 B frags, uint4-grouped
__device__ __align__(16) float gW2[3 * CCONST * DC];
__device__ __align__(16) float gBase[SZ * 3 * DC];

__device__ __forceinline__ uint32_t smem_u32(const void* p) {
    uint32_t a;
    asm("{ .reg .u64 t; cvta.to.shared.u64 t, %1; cvt.u32.u64 %0, t; }" : "=r"(a) : "l"(p));
    return a;
}
#define CP16(dst_u32, src_ptr) \
    asm volatile("cp.async.cg.shared.global [%0], [%1], 16;" :: "r"(dst_u32), "l"(src_ptr) : "memory")
#define CP_COMMIT() asm volatile("cp.async.commit_group;" ::: "memory")
#define CP_WAIT0()  asm volatile("cp.async.wait_group 0;" ::: "memory")
#define LDSM4(r0, r1, r2, r3, addr) \
    asm volatile("ldmatrix.sync.aligned.m8n8.x4.shared.b16 {%0,%1,%2,%3}, [%4];" \
        : "=r"(r0), "=r"(r1), "=r"(r2), "=r"(r3) : "r"(addr))
#define MMA_F16(d, a0, a1, a2, a3, bx, by) \
    asm volatile("mma.sync.aligned.m16n8k16.row.col.f32.f16.f16.f32 " \
        "{%0,%1,%2,%3},{%4,%5,%6,%7},{%8,%9},{%0,%1,%2,%3};" \
        : "+f"(d[0]), "+f"(d[1]), "+f"(d[2]), "+f"(d[3]) \
        : "r"(a0), "r"(a1), "r"(a2), "r"(a3), "r"(bx), "r"(by))

// ============================================================================
// P0: fp16 B fragments grouped for LDS.128 (unchanged layout) + gW2.
// ============================================================================
__global__ void prep_kernel(const float* __restrict__ conv_w) {
    int idx = blockIdx.x * blockDim.x + threadIdx.x;
    if (idx < KT * 16 * 32 * 2) {
        int r = idx & 1, lane = (idx >> 1) & 31, nt = (idx >> 6) & 15, kt = idx >> 10;
        int o = nt * 8 + (lane >> 2);
        int j0 = kt * 16 + (lane & 3) * 2 + r * 8;
        float v0 = 0.f, v1 = 0.f;
        { int tap = j0 / 112, c = j0 % 112; if (c < 110) v0 = conv_w[o * 810 + c * 3 + tap]; }
        { int j1 = j0 + 1; int tap = j1 / 112, c = j1 % 112; if (c < 110) v1 = conv_w[o * 810 + c * 3 + tap]; }
        __half2 h = __floats2half2_rn(v0, v1);
        gBfh[((kt * 8 + (nt >> 1)) * 32 + lane) * 4 + (nt & 1) * 2 + r] = *(uint32_t*)&h;
    } else {
        int i2 = idx - KT * 16 * 32 * 2;
        if (i2 < 3 * CCONST * DC) {
            int kc = i2 / DC, o = i2 % DC;
            int k = kc / CCONST, c2 = kc % CCONST;
            gW2[i2] = conv_w[o * 810 + (110 + c2) * 3 + k];
        }
    }
}

// ============================================================================
// P1: constant-channel base + loc branch (exact fp32, unchanged).
// ============================================================================
__global__ __launch_bounds__(256) void const_kernel(
    const int* __restrict__ loc, const int* __restrict__ loc_mark,
    const int* __restrict__ subtype, const int* __restrict__ argRole,
    const float* __restrict__ word_emb, const float* __restrict__ event_emb,
    const float* __restrict__ role_emb, float* __restrict__ out)
{
    __shared__ float evrl[GS][CCONST];
    int tid = threadIdx.x;
    int b0 = blockIdx.x * GS;
    for (int i = tid; i < GS * CCONST; i += 256) {
        int g = i / CCONST, c2 = i % CCONST;
        int b = b0 + g;
        float v;
        if (c2 < 32) v = event_emb[subtype[b] * 32 + c2];
        else { int r = (c2 - 32) >> 4, q = (c2 - 32) & 15; v = role_emb[argRole[b * 8 + r] * 16 + q]; }
        evrl[g][c2] = v;
    }
    __syncthreads();
    for (int t = tid; t < 3 * DC; t += 256) {
        int o = t % DC, k = t / DC;
        float s[GS];
        #pragma unroll
        for (int g = 0; g < GS; g++) s[g] = 0.f;
        const float* w2 = &gW2[k * CCONST * DC + o];
        for (int c2 = 0; c2 < CCONST; c2++) {
            float w = w2[c2 * DC];
            #pragma unroll
            for (int g = 0; g < GS; g++) s[g] = fmaf(evrl[g][c2], w, s[g]);
        }
        #pragma unroll
        for (int g = 0; g < GS; g++) gBase[(size_t)(b0 + g) * (3 * DC) + t] = s[g];
    }
    int g = tid >> 5, lane = tid & 31;
    int b = b0 + g;
    const int* lb = &loc[b * 16];
    int mark = loc_mark[b];
    float* ob = &out[(size_t)b * OUTD + 384];
    for (int d = lane; d < 100; d += 32) {
        #pragma unroll
        for (int i = 0; i < 4; i++) ob[i * 100 + d] = tanhf(word_emb[lb[i] * 100 + d]);
        float s = 0.f;
        for (int i = 0; i < mark; i++) s += word_emb[lb[4 + i] * 100 + d];
        ob[400 + d] = tanhf(s / (float)mark);
        ob[500 + d] = tanhf(word_emb[lb[4 + mark] * 100 + d]);
    }
}

// ============================================================================
// v-tile gather (s-major rows): row x = s+1, halves [c]; 8B store per float4.
// ============================================================================
__device__ __forceinline__ void gather_pair(
    char* smb, int pr, int buf, int tid,
    const int* __restrict__ inp, const int* __restrict__ pos1, const int* __restrict__ pos2,
    const float* __restrict__ word_emb, const float* __restrict__ pos_emb)
{
    #pragma unroll
    for (int sm = 0; sm < 2; sm++) {
        const int b = 2 * pr + sm;
        char* base = smb + SMB_VH + (buf * 2 + sm) * VH_BYTES;
        const int* inpb = inp + b * SEN;
        for (int idx = tid; idx < SEN * 25; idx += 512) {
            int s = idx / 25, q4 = idx % 25;
            float4 w4 = ((const float4*)word_emb)[(size_t)inpb[s] * 25 + q4];
            __half2 h01 = __floats2half2_rn(w4.x, w4.y);
            __half2 h23 = __floats2half2_rn(w4.z, w4.w);
            uint2 val = make_uint2(*(uint32_t*)&h01, *(uint32_t*)&h23);
            *(uint2*)(base + (s + 1) * VROWB + q4 * 8) = val;
        }
        const int* p1b = pos1 + b * SEN;
        const int* p2b = pos2 + b * SEN;
        for (int idx = tid; idx < SEN * 10; idx += 512) {
            int s = idx / 10, r = idx % 10;
            int row = (r < 5) ? p1b[s] : p2b[s];
            *(__half*)(base + (s + 1) * VROWB + (100 + r) * 2) =
                __float2half_rn(pos_emb[row * 5 + (r % 5)]);
        }
    }
}

// ============================================================================
// stage masks (as 0/1 bytes) + combined bias for one pair into buffer `buf`.
// Unsynced; visibility provided by the end-of-iteration barrier.
// ============================================================================
__device__ __forceinline__ void stage_pair(
    char* smb, int pr, int buf, int tid,
    const float* __restrict__ maskL, const float* __restrict__ maskM,
    const float* __restrict__ maskR, const float* __restrict__ conv_b)
{
    #pragma unroll
    for (int sm = 0; sm < 2; sm++) {
        const int b = 2 * pr + sm;
        uint8_t* mdst = (uint8_t*)(smb + SMB_MASK) + (buf * 2 + sm) * 384;
        for (int i = tid; i < 3 * SEN; i += 512) {
            float v = (i < 128) ? maskL[b * SEN + i]
                    : (i < 256) ? maskM[b * SEN + i - 128]
                                : maskR[b * SEN + i - 256];
            mdst[i] = (v != 0.f) ? 1 : 0;
        }
        float* cb = (float*)(smb + SMB_CB) + (buf * 2 + sm) * 384;
        if (tid < DC) {
            float b0v = gBase[(size_t)b * 384 + tid];
            float b1v = gBase[(size_t)b * 384 + 128 + tid];
            float b2v = gBase[(size_t)b * 384 + 256 + tid];
            cb[tid]       = conv_b[tid] + b0v + b1v + b2v;
            cb[128 + tid] = b0v;
            cb[256 + tid] = b2v;
        }
    }
}

// ============================================================================
// Main: 148 persistent CTAs (512 thr). B resident; 2 samples/iter; v-tiles
// AND mask/bias staging double-buffered one iteration ahead -> NO barrier
// between mainloop and epilogue, so epilogue ALU overlaps other warps' HMMA.
// Warp grid 4(M) x 4(N); A via ldmatrix.x4.
// ============================================================================
__global__ __launch_bounds__(512, 1) void main_kernel(
    const int* __restrict__ inp, const int* __restrict__ pos1, const int* __restrict__ pos2,
    const float* __restrict__ maskL, const float* __restrict__ maskM, const float* __restrict__ maskR,
    const float* __restrict__ word_emb, const float* __restrict__ pos_emb,
    const float* __restrict__ conv_b, float* __restrict__ out)
{
    extern __shared__ char smb[];
    float* sR = (float*)(smb + SMB_R);      // [sm][384][4]

    const int tid = threadIdx.x;
    const int lane = tid & 31, warp = tid >> 5;
    const int warp_m = warp & 3, warp_n = warp >> 2;
    const uint32_t smb_u = smem_u32(smb);

    // ---- one-time: load B (84KB), zero all 4 v tiles, stage+gather pair 0 ----
    {
        uint32_t dst = smb_u + SMB_B;
        const uint32_t* src = gBfh;
        for (int i = tid; i < KT * 8 * 32 * 4 / 4; i += 512)
            CP16(dst + i * 16, src + i * 4);
        CP_COMMIT();
    }
    for (int i = tid; i < 4 * VH_BYTES / 4; i += 512)
        ((uint32_t*)(smb + SMB_VH))[i] = 0u;
    CP_WAIT0();
    __syncthreads();
    if (blockIdx.x < SZ / 2) {
        gather_pair(smb, blockIdx.x, 0, tid, inp, pos1, pos2, word_emb, pos_emb);
        stage_pair(smb, blockIdx.x, 0, tid, maskL, maskM, maskR, conv_b);
    }
    __syncthreads();

    // per-thread ldmatrix lane address part: row (lane&15), k-half block (lane>>4)*16B
    const uint32_t rowsel = (uint32_t)((lane & 15) * VROWB + ((lane >> 4) << 4));

    int it = 0;
    for (int p = blockIdx.x; p < SZ / 2; p += gridDim.x, ++it) {
        const int cur = it & 1;
        const int bs[2] = { 2 * p, 2 * p + 1 };

        // ---- prefetch NEXT pair: v tiles + masks/bias (unsynced) ----
        if (p + gridDim.x < SZ / 2) {
            gather_pair(smb, p + gridDim.x, cur ^ 1, tid, inp, pos1, pos2, word_emb, pos_emb);
            stage_pair(smb, p + gridDim.x, cur ^ 1, tid, maskL, maskM, maskR, conv_b);
        }

        // ---- GEMM mainloop on current buffers ----
        float acc[2][2][4][4];
        #pragma unroll
        for (int sm = 0; sm < 2; sm++)
            #pragma unroll
            for (int mt = 0; mt < 2; mt++)
                #pragma unroll
                for (int nt = 0; nt < 4; nt++)
                    #pragma unroll
                    for (int r = 0; r < 4; r++) acc[sm][mt][nt][r] = 0.f;

        const uint32_t vb0 = smb_u + SMB_VH + (cur * 2 + 0) * VH_BYTES + rowsel;
        const uint32_t vb1 = smb_u + SMB_VH + (cur * 2 + 1) * VH_BYTES + rowsel;
        const uint4* sB4 = (const uint4*)(smb + SMB_B);

        #pragma unroll
        for (int tap = 0; tap < 3; tap++) {
            #pragma unroll
            for (int ktl = 0; ktl < 7; ktl++) {
                const int kt = tap * 7 + ktl;
                const uint32_t roff = (uint32_t)((warp_m * 32 + tap) * VROWB + ktl * 32);
                uint32_t am[2][2][4];
                LDSM4(am[0][0][0], am[0][0][1], am[0][0][2], am[0][0][3], vb0 + roff);
                LDSM4(am[0][1][0], am[0][1][1], am[0][1][2], am[0][1][3], vb0 + roff + 16 * VROWB);
                LDSM4(am[1][0][0], am[1][0][1], am[1][0][2], am[1][0][3], vb1 + roff);
                LDSM4(am[1][1][0], am[1][1][1], am[1][1][2], am[1][1][3], vb1 + roff + 16 * VROWB);
                const uint4* bw = sB4 + kt * 256 + (warp_n * 2) * 32;
                uint4 bb0 = bw[lane];
                uint4 bb1 = bw[32 + lane];
                #pragma unroll
                for (int sm = 0; sm < 2; sm++) {
                    #pragma unroll
                    for (int mt = 0; mt < 2; mt++) {
                        MMA_F16(acc[sm][mt][0], am[sm][mt][0], am[sm][mt][1], am[sm][mt][2], am[sm][mt][3], bb0.x, bb0.y);
                        MMA_F16(acc[sm][mt][1], am[sm][mt][0], am[sm][mt][1], am[sm][mt][2], am[sm][mt][3], bb0.z, bb0.w);
                        MMA_F16(acc[sm][mt][2], am[sm][mt][0], am[sm][mt][1], am[sm][mt][2], am[sm][mt][3], bb1.x, bb1.y);
                        MMA_F16(acc[sm][mt][3], am[sm][mt][0], am[sm][mt][1], am[sm][mt][2], am[sm][mt][3], bb1.z, bb1.w);
                    }
                }
            }
        }

        // ---- epilogue (NO barrier: staging visible since last iter's bar) ----
        #pragma unroll
        for (int sm = 0; sm < 2; sm++) {
            const uint8_t* mp = (const uint8_t*)(smb + SMB_MASK) + (cur * 2 + sm) * 384;
            const float* cb = (const float*)(smb + SMB_CB) + (cur * 2 + sm) * 384;
            bool mz[3][4];
            int srow[4];
            #pragma unroll
            for (int mt = 0; mt < 2; mt++)
                #pragma unroll
                for (int rg = 0; rg < 2; rg++) {
                    int s = warp_m * 32 + mt * 16 + (lane >> 2) + rg * 8;
                    int q = mt * 2 + rg;
                    srow[q] = s;
                    mz[0][q] = mp[s] != 0;
                    mz[1][q] = mp[128 + s] != 0;
                    mz[2][q] = mp[256 + s] != 0;
                }
            #pragma unroll
            for (int nt = 0; nt < 4; nt++) {
                #pragma unroll
                for (int h = 0; h < 2; h++) {
                    int o = warp_n * 32 + nt * 8 + 2 * (lane & 3) + h;
                    float C = cb[o], B0v = cb[128 + o], B2v = cb[256 + o];
                    float p0 = -3.0e38f, p1 = -3.0e38f, p2 = -3.0e38f;
                    #pragma unroll
                    for (int mt = 0; mt < 2; mt++)
                        #pragma unroll
                        for (int rg = 0; rg < 2; rg++) {
                            int q = mt * 2 + rg;
                            int s = srow[q];
                            float cv = acc[sm][mt][nt][rg * 2 + h] + C;
                            if (s == 0)   cv -= B0v;
                            if (s == 127) cv -= B2v;
                            p0 = fmaxf(p0, mz[0][q] ? cv : 0.0f);
                            p1 = fmaxf(p1, mz[1][q] ? cv : 0.0f);
                            p2 = fmaxf(p2, mz[2][q] ? cv : 0.0f);
                        }
                    #pragma unroll
                    for (int off = 4; off <= 16; off <<= 1) {
                        p0 = fmaxf(p0, __shfl_xor_sync(0xffffffffu, p0, off));
                        p1 = fmaxf(p1, __shfl_xor_sync(0xffffffffu, p1, off));
                        p2 = fmaxf(p2, __shfl_xor_sync(0xffffffffu, p2, off));
                    }
                    if ((lane & 28) == 0) {
                        sR[((sm * 384 + 0 * 128 + o) << 2) + warp_m] = p0;
                        sR[((sm * 384 + 1 * 128 + o) << 2) + warp_m] = p1;
                        sR[((sm * 384 + 2 * 128 + o) << 2) + warp_m] = p2;
                    }
                }
            }
        }
        __syncthreads();   // sR complete

        for (int t = tid; t < 2 * 384; t += 512) {
            int sm = t / 384, tt = t % 384;
            const float* rp = &sR[t << 2];
            float R = fmaxf(fmaxf(rp[0], rp[1]), fmaxf(rp[2], rp[3]));
            out[(size_t)bs[sm] * OUTD + tt] = tanhf(R);
        }
        __syncthreads();   // sR consumed; buffers swap
    }
}

// ============================================================================
extern "C" void kernel_launch(void* const* d_in, const int* in_sizes, int n_in,
                              void* d_out, int out_size) {
    const int*   inp       = (const int*)d_in[0];
    const int*   pos1      = (const int*)d_in[1];
    const int*   pos2      = (const int*)d_in[2];
    const int*   loc       = (const int*)d_in[3];
    const int*   loc_mark  = (const int*)d_in[4];
    const int*   subtype   = (const int*)d_in[5];
    const int*   argRole   = (const int*)d_in[6];
    const float* maskL     = (const float*)d_in[7];
    const float* maskM     = (const float*)d_in[8];
    const float* maskR     = (const float*)d_in[9];
    const float* word_emb  = (const float*)d_in[10];
    const float* pos_emb   = (const float*)d_in[11];
    const float* event_emb = (const float*)d_in[12];
    const float* role_emb  = (const float*)d_in[13];
    const float* conv_w    = (const float*)d_in[14];
    const float* conv_b    = (const float*)d_in[15];
    float* out = (float*)d_out;

    int prep_elems = KT * 16 * 32 * 2 + 3 * CCONST * DC;
    prep_kernel<<<(prep_elems + 255) / 256, 256>>>(conv_w);
    const_kernel<<<SZ / GS, 256>>>(loc, loc_mark, subtype, argRole,
                                   word_emb, event_emb, role_emb, out);
    cudaFuncSetAttribute(main_kernel, cudaFuncAttributeMaxDynamicSharedMemorySize, SMB_TOT);
    main_kernel<<<148, 512, SMB_TOT>>>(inp, pos1, pos2, maskL, maskM, maskR,
                                       word_emb, pos_emb, conv_b, out);
}

// round 12
// speedup vs baseline: 1.0465x; 1.0465x over previous
#include <cuda_runtime.h>
#include <cuda_fp16.h>
#include <math.h>
#include <stdint.h>

#define SZ     4096
#define SEN    128
#define DC     128
#define OUTD   984
#define CCONST 160
#define GS     8
#define KT     21             // k16 steps = 3 taps * 7
#define VROWB  240            // bytes per v-tile row: 120 halves (112 data + 8 pad)
#define VH_BYTES (130 * VROWB)   // 31200 per sample tile (rows x = 0..129)

// SMEM byte offsets
#define SMB_B    0                      // 21*8*32 uint4 = 86016
#define SMB_VH   86016                  // 4 tiles * 31200 = 124800
#define SMB_MASK 210816                 // 2*384 f = 3072
#define SMB_C    213888                 // 2*128 f = 1024
#define SMB_B0   214912                 // 1024
#define SMB_B2   215936                 // 1024
#define SMB_R    216960                 // 2*384*4 f = 12288
#define SMB_TOT  229248

typedef unsigned long long u64;

__device__ __align__(16) uint32_t gBfh[KT * 8 * 32 * 4];   // fp16 B frags, uint4-grouped
__device__ __align__(16) float gW2[3 * CCONST * DC];
__device__ __align__(16) float gBase[SZ * 3 * DC];

__device__ __forceinline__ uint32_t smem_u32(const void* p) {
    uint32_t a;
    asm("{ .reg .u64 t; cvta.to.shared.u64 t, %1; cvt.u32.u64 %0, t; }" : "=r"(a) : "l"(p));
    return a;
}
#define CP16(dst_u32, src_ptr) \
    asm volatile("cp.async.cg.shared.global [%0], [%1], 16;" :: "r"(dst_u32), "l"(src_ptr) : "memory")
#define CP_COMMIT() asm volatile("cp.async.commit_group;" ::: "memory")
#define CP_WAIT0()  asm volatile("cp.async.wait_group 0;" ::: "memory")
#define LDSM4(r0, r1, r2, r3, addr) \
    asm volatile("ldmatrix.sync.aligned.m8n8.x4.shared.b16 {%0,%1,%2,%3}, [%4];" \
        : "=r"(r0), "=r"(r1), "=r"(r2), "=r"(r3) : "r"(addr))
// fp16-accumulate HMMA: D(=C) is 2x f16x2 regs
#define MMA_H16(d, a0, a1, a2, a3, bx, by) \
    asm volatile("mma.sync.aligned.m16n8k16.row.col.f16.f16.f16.f16 " \
        "{%0,%1},{%2,%3,%4,%5},{%6,%7},{%0,%1};" \
        : "+r"(d[0]), "+r"(d[1]) \
        : "r"(a0), "r"(a1), "r"(a2), "r"(a3), "r"(bx), "r"(by))

// ============================================================================
// P0: fp16 B fragments grouped for LDS.128 (unchanged layout) + gW2.
// ============================================================================
__global__ void prep_kernel(const float* __restrict__ conv_w) {
    int idx = blockIdx.x * blockDim.x + threadIdx.x;
    if (idx < KT * 16 * 32 * 2) {
        int r = idx & 1, lane = (idx >> 1) & 31, nt = (idx >> 6) & 15, kt = idx >> 10;
        int o = nt * 8 + (lane >> 2);
        int j0 = kt * 16 + (lane & 3) * 2 + r * 8;
        float v0 = 0.f, v1 = 0.f;
        { int tap = j0 / 112, c = j0 % 112; if (c < 110) v0 = conv_w[o * 810 + c * 3 + tap]; }
        { int j1 = j0 + 1; int tap = j1 / 112, c = j1 % 112; if (c < 110) v1 = conv_w[o * 810 + c * 3 + tap]; }
        __half2 h = __floats2half2_rn(v0, v1);
        gBfh[((kt * 8 + (nt >> 1)) * 32 + lane) * 4 + (nt & 1) * 2 + r] = *(uint32_t*)&h;
    } else {
        int i2 = idx - KT * 16 * 32 * 2;
        if (i2 < 3 * CCONST * DC) {
            int kc = i2 / DC, o = i2 % DC;
            int k = kc / CCONST, c2 = kc % CCONST;
            gW2[i2] = conv_w[o * 810 + (110 + c2) * 3 + k];
        }
    }
}

// ============================================================================
// P1: constant-channel base + loc branch (exact fp32, unchanged).
// ============================================================================
__global__ __launch_bounds__(256) void const_kernel(
    const int* __restrict__ loc, const int* __restrict__ loc_mark,
    const int* __restrict__ subtype, const int* __restrict__ argRole,
    const float* __restrict__ word_emb, const float* __restrict__ event_emb,
    const float* __restrict__ role_emb, float* __restrict__ out)
{
    __shared__ float evrl[GS][CCONST];
    int tid = threadIdx.x;
    int b0 = blockIdx.x * GS;
    for (int i = tid; i < GS * CCONST; i += 256) {
        int g = i / CCONST, c2 = i % CCONST;
        int b = b0 + g;
        float v;
        if (c2 < 32) v = event_emb[subtype[b] * 32 + c2];
        else { int r = (c2 - 32) >> 4, q = (c2 - 32) & 15; v = role_emb[argRole[b * 8 + r] * 16 + q]; }
        evrl[g][c2] = v;
    }
    __syncthreads();
    for (int t = tid; t < 3 * DC; t += 256) {
        int o = t % DC, k = t / DC;
        float s[GS];
        #pragma unroll
        for (int g = 0; g < GS; g++) s[g] = 0.f;
        const float* w2 = &gW2[k * CCONST * DC + o];
        for (int c2 = 0; c2 < CCONST; c2++) {
            float w = w2[c2 * DC];
            #pragma unroll
            for (int g = 0; g < GS; g++) s[g] = fmaf(evrl[g][c2], w, s[g]);
        }
        #pragma unroll
        for (int g = 0; g < GS; g++) gBase[(size_t)(b0 + g) * (3 * DC) + t] = s[g];
    }
    int g = tid >> 5, lane = tid & 31;
    int b = b0 + g;
    const int* lb = &loc[b * 16];
    int mark = loc_mark[b];
    float* ob = &out[(size_t)b * OUTD + 384];
    for (int d = lane; d < 100; d += 32) {
        #pragma unroll
        for (int i = 0; i < 4; i++) ob[i * 100 + d] = tanhf(word_emb[lb[i] * 100 + d]);
        float s = 0.f;
        for (int i = 0; i < mark; i++) s += word_emb[lb[4 + i] * 100 + d];
        ob[400 + d] = tanhf(s / (float)mark);
        ob[500 + d] = tanhf(word_emb[lb[4 + mark] * 100 + d]);
    }
}

// ============================================================================
// v-tile gather (s-major rows): row x = s+1, halves [c]; 8B store per float4.
// ============================================================================
__device__ __forceinline__ void gather_pair(
    char* smb, int pr, int buf, int tid,
    const int* __restrict__ inp, const int* __restrict__ pos1, const int* __restrict__ pos2,
    const float* __restrict__ word_emb, const float* __restrict__ pos_emb)
{
    #pragma unroll
    for (int sm = 0; sm < 2; sm++) {
        const int b = 2 * pr + sm;
        char* base = smb + SMB_VH + (buf * 2 + sm) * VH_BYTES;
        const int* inpb = inp + b * SEN;
        for (int idx = tid; idx < SEN * 25; idx += 512) {
            int s = idx / 25, q4 = idx % 25;
            float4 w4 = ((const float4*)word_emb)[(size_t)inpb[s] * 25 + q4];
            __half2 h01 = __floats2half2_rn(w4.x, w4.y);
            __half2 h23 = __floats2half2_rn(w4.z, w4.w);
            uint2 val = make_uint2(*(uint32_t*)&h01, *(uint32_t*)&h23);
            *(uint2*)(base + (s + 1) * VROWB + q4 * 8) = val;
        }
        const int* p1b = pos1 + b * SEN;
        const int* p2b = pos2 + b * SEN;
        for (int idx = tid; idx < SEN * 10; idx += 512) {
            int s = idx / 10, r = idx % 10;
            int row = (r < 5) ? p1b[s] : p2b[s];
            *(__half*)(base + (s + 1) * VROWB + (100 + r) * 2) =
                __float2half_rn(pos_emb[row * 5 + (r % 5)]);
        }
    }
}

// ============================================================================
// Main: 148 persistent CTAs (512 thr). R10 structure (barrier kept, prefetch
// kept, ldmatrix A). NEW: fp16-accumulate HMMA within each tap (7 ksteps),
// flushed to fp32 totals at tap boundaries.
// ============================================================================
__global__ __launch_bounds__(512, 1) void main_kernel(
    const int* __restrict__ inp, const int* __restrict__ pos1, const int* __restrict__ pos2,
    const float* __restrict__ maskL, const float* __restrict__ maskM, const float* __restrict__ maskR,
    const float* __restrict__ word_emb, const float* __restrict__ pos_emb,
    const float* __restrict__ conv_b, float* __restrict__ out)
{
    extern __shared__ char smb[];
    float* sMask = (float*)(smb + SMB_MASK);   // [sm][3*128]
    float* sC    = (float*)(smb + SMB_C);      // [sm][128]
    float* sB0   = (float*)(smb + SMB_B0);
    float* sB2   = (float*)(smb + SMB_B2);
    float* sR    = (float*)(smb + SMB_R);      // [sm][384][4]

    const int tid = threadIdx.x;
    const int lane = tid & 31, warp = tid >> 5;
    const int warp_m = warp & 3, warp_n = warp >> 2;
    const uint32_t smb_u = smem_u32(smb);

    // ---- one-time: load B (84KB), zero all 4 v tiles, gather first pair ----
    {
        uint32_t dst = smb_u + SMB_B;
        const uint32_t* src = gBfh;
        for (int i = tid; i < KT * 8 * 32 * 4 / 4; i += 512)
            CP16(dst + i * 16, src + i * 4);
        CP_COMMIT();
    }
    for (int i = tid; i < 4 * VH_BYTES / 4; i += 512)
        ((uint32_t*)(smb + SMB_VH))[i] = 0u;
    CP_WAIT0();
    __syncthreads();
    if (blockIdx.x < SZ / 2)
        gather_pair(smb, blockIdx.x, 0, tid, inp, pos1, pos2, word_emb, pos_emb);
    __syncthreads();

    // per-thread ldmatrix lane address part: row (lane&15), k-half block (lane>>4)*16B
    const uint32_t rowsel = (uint32_t)((lane & 15) * VROWB + ((lane >> 4) << 4));

    int it = 0;
    for (int p = blockIdx.x; p < SZ / 2; p += gridDim.x, ++it) {
        const int cur = it & 1;
        const int bs[2] = { 2 * p, 2 * p + 1 };

        // ---- stage masks + bias (unsynced; visible after post-mainloop bar) ----
        #pragma unroll
        for (int sm = 0; sm < 2; sm++) {
            const int b = bs[sm];
            for (int i = tid; i < 3 * SEN; i += 512) {
                sMask[sm * 384 + i] =
                      (i < 128) ? maskL[b * SEN + i]
                    : (i < 256) ? maskM[b * SEN + i - 128]
                                : maskR[b * SEN + i - 256];
            }
            if (tid < DC) {
                float b0v = gBase[(size_t)b * 384 + tid];
                float b1v = gBase[(size_t)b * 384 + 128 + tid];
                float b2v = gBase[(size_t)b * 384 + 256 + tid];
                sC[sm * 128 + tid] = conv_b[tid] + b0v + b1v + b2v;
                sB0[sm * 128 + tid] = b0v;
                sB2[sm * 128 + tid] = b2v;
            }
        }

        // ---- prefetch next pair's v tiles ----
        if (p + gridDim.x < SZ / 2)
            gather_pair(smb, p + gridDim.x, cur ^ 1, tid, inp, pos1, pos2, word_emb, pos_emb);

        // ---- GEMM mainloop: f16-acc within tap, f32 totals across taps ----
        float acc[2][2][4][4];
        #pragma unroll
        for (int sm = 0; sm < 2; sm++)
            #pragma unroll
            for (int mt = 0; mt < 2; mt++)
                #pragma unroll
                for (int nt = 0; nt < 4; nt++)
                    #pragma unroll
                    for (int r = 0; r < 4; r++) acc[sm][mt][nt][r] = 0.f;

        const uint32_t vb0 = smb_u + SMB_VH + (cur * 2 + 0) * VH_BYTES + rowsel;
        const uint32_t vb1 = smb_u + SMB_VH + (cur * 2 + 1) * VH_BYTES + rowsel;
        const uint4* sB4 = (const uint4*)(smb + SMB_B);

        #pragma unroll
        for (int tap = 0; tap < 3; tap++) {
            uint32_t hacc[2][2][4][2];
            #pragma unroll
            for (int sm = 0; sm < 2; sm++)
                #pragma unroll
                for (int mt = 0; mt < 2; mt++)
                    #pragma unroll
                    for (int nt = 0; nt < 4; nt++) {
                        hacc[sm][mt][nt][0] = 0u;
                        hacc[sm][mt][nt][1] = 0u;
                    }
            #pragma unroll
            for (int ktl = 0; ktl < 7; ktl++) {
                const int kt = tap * 7 + ktl;
                const uint32_t roff = (uint32_t)((warp_m * 32 + tap) * VROWB + ktl * 32);
                uint32_t am[2][2][4];
                LDSM4(am[0][0][0], am[0][0][1], am[0][0][2], am[0][0][3], vb0 + roff);
                LDSM4(am[0][1][0], am[0][1][1], am[0][1][2], am[0][1][3], vb0 + roff + 16 * VROWB);
                LDSM4(am[1][0][0], am[1][0][1], am[1][0][2], am[1][0][3], vb1 + roff);
                LDSM4(am[1][1][0], am[1][1][1], am[1][1][2], am[1][1][3], vb1 + roff + 16 * VROWB);
                const uint4* bw = sB4 + kt * 256 + (warp_n * 2) * 32;
                uint4 bb0 = bw[lane];
                uint4 bb1 = bw[32 + lane];
                #pragma unroll
                for (int sm = 0; sm < 2; sm++) {
                    #pragma unroll
                    for (int mt = 0; mt < 2; mt++) {
                        MMA_H16(hacc[sm][mt][0], am[sm][mt][0], am[sm][mt][1], am[sm][mt][2], am[sm][mt][3], bb0.x, bb0.y);
                        MMA_H16(hacc[sm][mt][1], am[sm][mt][0], am[sm][mt][1], am[sm][mt][2], am[sm][mt][3], bb0.z, bb0.w);
                        MMA_H16(hacc[sm][mt][2], am[sm][mt][0], am[sm][mt][1], am[sm][mt][2], am[sm][mt][3], bb1.x, bb1.y);
                        MMA_H16(hacc[sm][mt][3], am[sm][mt][0], am[sm][mt][1], am[sm][mt][2], am[sm][mt][3], bb1.z, bb1.w);
                    }
                }
            }
            // flush tap's f16 partials into f32 totals
            #pragma unroll
            for (int sm = 0; sm < 2; sm++)
                #pragma unroll
                for (int mt = 0; mt < 2; mt++)
                    #pragma unroll
                    for (int nt = 0; nt < 4; nt++) {
                        float2 f0 = __half22float2(*(__half2*)&hacc[sm][mt][nt][0]);
                        float2 f1 = __half22float2(*(__half2*)&hacc[sm][mt][nt][1]);
                        acc[sm][mt][nt][0] += f0.x;
                        acc[sm][mt][nt][1] += f0.y;
                        acc[sm][mt][nt][2] += f1.x;
                        acc[sm][mt][nt][3] += f1.y;
                    }
        }

        __syncthreads();   // masks/bias visible; prefetch long since done

        // ---- epilogue per sample (identical to R10) ----
        #pragma unroll
        for (int sm = 0; sm < 2; sm++) {
            float mv[3][4];
            int srow[4];
            #pragma unroll
            for (int mt = 0; mt < 2; mt++)
                #pragma unroll
                for (int rg = 0; rg < 2; rg++) {
                    int s = warp_m * 32 + mt * 16 + (lane >> 2) + rg * 8;
                    int q = mt * 2 + rg;
                    srow[q] = s;
                    mv[0][q] = sMask[sm * 384 + s];
                    mv[1][q] = sMask[sm * 384 + 128 + s];
                    mv[2][q] = sMask[sm * 384 + 256 + s];
                }
            #pragma unroll
            for (int nt = 0; nt < 4; nt++) {
                #pragma unroll
                for (int h = 0; h < 2; h++) {
                    int o = warp_n * 32 + nt * 8 + 2 * (lane & 3) + h;
                    float C = sC[sm * 128 + o];
                    float B0v = sB0[sm * 128 + o], B2v = sB2[sm * 128 + o];
                    float p0 = -3.0e38f, p1 = -3.0e38f, p2 = -3.0e38f;
                    #pragma unroll
                    for (int mt = 0; mt < 2; mt++)
                        #pragma unroll
                        for (int rg = 0; rg < 2; rg++) {
                            int q = mt * 2 + rg;
                            int s = srow[q];
                            float cv = acc[sm][mt][nt][rg * 2 + h] + C;
                            if (s == 0)   cv -= B0v;
                            if (s == 127) cv -= B2v;
                            p0 = fmaxf(p0, cv * mv[0][q]);
                            p1 = fmaxf(p1, cv * mv[1][q]);
                            p2 = fmaxf(p2, cv * mv[2][q]);
                        }
                    #pragma unroll
                    for (int off = 4; off <= 16; off <<= 1) {
                        p0 = fmaxf(p0, __shfl_xor_sync(0xffffffffu, p0, off));
                        p1 = fmaxf(p1, __shfl_xor_sync(0xffffffffu, p1, off));
                        p2 = fmaxf(p2, __shfl_xor_sync(0xffffffffu, p2, off));
                    }
                    if ((lane & 28) == 0) {
                        sR[((sm * 384 + 0 * 128 + o) << 2) + warp_m] = p0;
                        sR[((sm * 384 + 1 * 128 + o) << 2) + warp_m] = p1;
                        sR[((sm * 384 + 2 * 128 + o) << 2) + warp_m] = p2;
                    }
                }
            }
        }
        __syncthreads();

        for (int t = tid; t < 2 * 384; t += 512) {
            int sm = t / 384, tt = t % 384;
            const float* rp = &sR[t << 2];
            float R = fmaxf(fmaxf(rp[0], rp[1]), fmaxf(rp[2], rp[3]));
            out[(size_t)bs[sm] * OUTD + tt] = tanhf(R);
        }
        __syncthreads();   // sR consumed; buffers swap
    }
}

// ============================================================================
extern "C" void kernel_launch(void* const* d_in, const int* in_sizes, int n_in,
                              void* d_out, int out_size) {
    const int*   inp       = (const int*)d_in[0];
    const int*   pos1      = (const int*)d_in[1];
    const int*   pos2      = (const int*)d_in[2];
    const int*   loc       = (const int*)d_in[3];
    const int*   loc_mark  = (const int*)d_in[4];
    const int*   subtype   = (const int*)d_in[5];
    const int*   argRole   = (const int*)d_in[6];
    const float* maskL     = (const float*)d_in[7];
    const float* maskM     = (const float*)d_in[8];
    const float* maskR     = (const float*)d_in[9];
    const float* word_emb  = (const float*)d_in[10];
    const float* pos_emb   = (const float*)d_in[11];
    const float* event_emb = (const float*)d_in[12];
    const float* role_emb  = (const float*)d_in[13];
    const float* conv_w    = (const float*)d_in[14];
    const float* conv_b    = (const float*)d_in[15];
    float* out = (float*)d_out;

    int prep_elems = KT * 16 * 32 * 2 + 3 * CCONST * DC;
    prep_kernel<<<(prep_elems + 255) / 256, 256>>>(conv_w);
    const_kernel<<<SZ / GS, 256>>>(loc, loc_mark, subtype, argRole,
                                   word_emb, event_emb, role_emb, out);
    cudaFuncSetAttribute(main_kernel, cudaFuncAttributeMaxDynamicSharedMemorySize, SMB_TOT);
    main_kernel<<<148, 512, SMB_TOT>>>(inp, pos1, pos2, maskL, maskM, maskR,
                                       word_emb, pos_emb, conv_b, out);
}

// round 13
// speedup vs baseline: 1.0950x; 1.0464x over previous
#include <cuda_runtime.h>
#include <cuda_fp16.h>
#include <math.h>
#include <stdint.h>

#define SZ     4096
#define SEN    128
#define DC     128
#define OUTD   984
#define CCONST 160
#define GS     8
#define KT     21             // k16 steps = 3 taps * 7
#define VROWB  240            // bytes per v-tile row: 120 halves (112 data + 8 pad)
#define VH_BYTES (130 * VROWB)   // 31200 per sample tile (rows x = 0..129)

// SMEM byte offsets
#define SMB_B    0                      // 21*8*32 uint4 = 86016
#define SMB_VH   86016                  // 4 tiles * 31200 = 124800 -> 210816
#define SMB_MASK 210816                 // 2 bufs * 2 sm * 384 half = 3072 -> 213888
#define SMB_CB   213888                 // 2 bufs * 2 sm * 384 f = 6144 -> 220032
#define SMB_R    220032                 // 2*384*4 f = 12288 -> 232320
#define SMB_TOT  232320

typedef unsigned long long u64;

__device__ __align__(16) uint32_t gBfh[KT * 8 * 32 * 4];   // fp16 B frags, uint4-grouped
__device__ __align__(16) float gW2[3 * CCONST * DC];
__device__ __align__(16) float gBase[SZ * 3 * DC];

__device__ __forceinline__ uint32_t smem_u32(const void* p) {
    uint32_t a;
    asm("{ .reg .u64 t; cvta.to.shared.u64 t, %1; cvt.u32.u64 %0, t; }" : "=r"(a) : "l"(p));
    return a;
}
#define CP16(dst_u32, src_ptr) \
    asm volatile("cp.async.cg.shared.global [%0], [%1], 16;" :: "r"(dst_u32), "l"(src_ptr) : "memory")
#define CP_COMMIT() asm volatile("cp.async.commit_group;" ::: "memory")
#define CP_WAIT0()  asm volatile("cp.async.wait_group 0;" ::: "memory")
#define LDSM4(r0, r1, r2, r3, addr) \
    asm volatile("ldmatrix.sync.aligned.m8n8.x4.shared.b16 {%0,%1,%2,%3}, [%4];" \
        : "=r"(r0), "=r"(r1), "=r"(r2), "=r"(r3) : "r"(addr))
#define MMA_F16(d, a0, a1, a2, a3, bx, by) \
    asm volatile("mma.sync.aligned.m16n8k16.row.col.f32.f16.f16.f32 " \
        "{%0,%1,%2,%3},{%4,%5,%6,%7},{%8,%9},{%0,%1,%2,%3};" \
        : "+f"(d[0]), "+f"(d[1]), "+f"(d[2]), "+f"(d[3]) \
        : "r"(a0), "r"(a1), "r"(a2), "r"(a3), "r"(bx), "r"(by))

// ============================================================================
// P0: fp16 B fragments grouped for LDS.128 (unchanged layout) + gW2.
// ============================================================================
__global__ void prep_kernel(const float* __restrict__ conv_w) {
    int idx = blockIdx.x * blockDim.x + threadIdx.x;
    if (idx < KT * 16 * 32 * 2) {
        int r = idx & 1, lane = (idx >> 1) & 31, nt = (idx >> 6) & 15, kt = idx >> 10;
        int o = nt * 8 + (lane >> 2);
        int j0 = kt * 16 + (lane & 3) * 2 + r * 8;
        float v0 = 0.f, v1 = 0.f;
        { int tap = j0 / 112, c = j0 % 112; if (c < 110) v0 = conv_w[o * 810 + c * 3 + tap]; }
        { int j1 = j0 + 1; int tap = j1 / 112, c = j1 % 112; if (c < 110) v1 = conv_w[o * 810 + c * 3 + tap]; }
        __half2 h = __floats2half2_rn(v0, v1);
        gBfh[((kt * 8 + (nt >> 1)) * 32 + lane) * 4 + (nt & 1) * 2 + r] = *(uint32_t*)&h;
    } else {
        int i2 = idx - KT * 16 * 32 * 2;
        if (i2 < 3 * CCONST * DC) {
            int kc = i2 / DC, o = i2 % DC;
            int k = kc / CCONST, c2 = kc % CCONST;
            gW2[i2] = conv_w[o * 810 + (110 + c2) * 3 + k];
        }
    }
}

// ============================================================================
// P1: constant-channel base + loc branch (exact fp32, unchanged).
// ============================================================================
__global__ __launch_bounds__(256) void const_kernel(
    const int* __restrict__ loc, const int* __restrict__ loc_mark,
    const int* __restrict__ subtype, const int* __restrict__ argRole,
    const float* __restrict__ word_emb, const float* __restrict__ event_emb,
    const float* __restrict__ role_emb, float* __restrict__ out)
{
    __shared__ float evrl[GS][CCONST];
    int tid = threadIdx.x;
    int b0 = blockIdx.x * GS;
    for (int i = tid; i < GS * CCONST; i += 256) {
        int g = i / CCONST, c2 = i % CCONST;
        int b = b0 + g;
        float v;
        if (c2 < 32) v = event_emb[subtype[b] * 32 + c2];
        else { int r = (c2 - 32) >> 4, q = (c2 - 32) & 15; v = role_emb[argRole[b * 8 + r] * 16 + q]; }
        evrl[g][c2] = v;
    }
    __syncthreads();
    for (int t = tid; t < 3 * DC; t += 256) {
        int o = t % DC, k = t / DC;
        float s[GS];
        #pragma unroll
        for (int g = 0; g < GS; g++) s[g] = 0.f;
        const float* w2 = &gW2[k * CCONST * DC + o];
        for (int c2 = 0; c2 < CCONST; c2++) {
            float w = w2[c2 * DC];
            #pragma unroll
            for (int g = 0; g < GS; g++) s[g] = fmaf(evrl[g][c2], w, s[g]);
        }
        #pragma unroll
        for (int g = 0; g < GS; g++) gBase[(size_t)(b0 + g) * (3 * DC) + t] = s[g];
    }
    int g = tid >> 5, lane = tid & 31;
    int b = b0 + g;
    const int* lb = &loc[b * 16];
    int mark = loc_mark[b];
    float* ob = &out[(size_t)b * OUTD + 384];
    for (int d = lane; d < 100; d += 32) {
        #pragma unroll
        for (int i = 0; i < 4; i++) ob[i * 100 + d] = tanhf(word_emb[lb[i] * 100 + d]);
        float s = 0.f;
        for (int i = 0; i < mark; i++) s += word_emb[lb[4 + i] * 100 + d];
        ob[400 + d] = tanhf(s / (float)mark);
        ob[500 + d] = tanhf(word_emb[lb[4 + mark] * 100 + d]);
    }
}

// ============================================================================
// v-tile gather (s-major rows): row x = s+1, halves [c]; 8B store per float4.
// ============================================================================
__device__ __forceinline__ void gather_pair(
    char* smb, int pr, int buf, int tid,
    const int* __restrict__ inp, const int* __restrict__ pos1, const int* __restrict__ pos2,
    const float* __restrict__ word_emb, const float* __restrict__ pos_emb)
{
    #pragma unroll
    for (int sm = 0; sm < 2; sm++) {
        const int b = 2 * pr + sm;
        char* base = smb + SMB_VH + (buf * 2 + sm) * VH_BYTES;
        const int* inpb = inp + b * SEN;
        for (int idx = tid; idx < SEN * 25; idx += 512) {
            int s = idx / 25, q4 = idx % 25;
            float4 w4 = ((const float4*)word_emb)[(size_t)inpb[s] * 25 + q4];
            __half2 h01 = __floats2half2_rn(w4.x, w4.y);
            __half2 h23 = __floats2half2_rn(w4.z, w4.w);
            uint2 val = make_uint2(*(uint32_t*)&h01, *(uint32_t*)&h23);
            *(uint2*)(base + (s + 1) * VROWB + q4 * 8) = val;
        }
        const int* p1b = pos1 + b * SEN;
        const int* p2b = pos2 + b * SEN;
        for (int idx = tid; idx < SEN * 10; idx += 512) {
            int s = idx / 10, r = idx % 10;
            int row = (r < 5) ? p1b[s] : p2b[s];
            *(__half*)(base + (s + 1) * VROWB + (100 + r) * 2) =
                __float2half_rn(pos_emb[row * 5 + (r % 5)]);
        }
    }
}

// ============================================================================
// stage masks (as half 0/1 — exact) + combined bias for one pair, buffer `buf`.
// Unsynced; visibility provided by the NEXT iteration's top barrier (B1).
// ============================================================================
__device__ __forceinline__ void stage_pair(
    char* smb, int pr, int buf, int tid,
    const float* __restrict__ maskL, const float* __restrict__ maskM,
    const float* __restrict__ maskR, const float* __restrict__ conv_b)
{
    #pragma unroll
    for (int sm = 0; sm < 2; sm++) {
        const int b = 2 * pr + sm;
        __half* mdst = (__half*)(smb + SMB_MASK) + (buf * 2 + sm) * 384;
        for (int i = tid; i < 3 * SEN; i += 512) {
            float v = (i < 128) ? maskL[b * SEN + i]
                    : (i < 256) ? maskM[b * SEN + i - 128]
                                : maskR[b * SEN + i - 256];
            mdst[i] = __float2half_rn(v);   // 0.0 / 1.0 exact in half
        }
        float* cb = (float*)(smb + SMB_CB) + (buf * 2 + sm) * 384;
        if (tid < DC) {
            float b0v = gBase[(size_t)b * 384 + tid];
            float b1v = gBase[(size_t)b * 384 + 128 + tid];
            float b2v = gBase[(size_t)b * 384 + 256 + tid];
            cb[tid]       = conv_b[tid] + b0v + b1v + b2v;
            cb[128 + tid] = b0v;
            cb[256 + tid] = b2v;
        }
    }
}

// ============================================================================
// Main: 148 persistent CTAs (512 thr). B resident; 2 samples/iter; v-tiles AND
// staging double-buffered one iteration ahead. Barrier placement: B1 at top of
// iteration (everything for pair p already resident), B2 between epilogue and
// sR combine. NO barrier between mainloop and epilogue -> epilogue ALU of each
// warp overlaps other warps' HMMA backpressure. Warp grid 4(M) x 4(N).
// ============================================================================
__global__ __launch_bounds__(512, 1) void main_kernel(
    const int* __restrict__ inp, const int* __restrict__ pos1, const int* __restrict__ pos2,
    const float* __restrict__ maskL, const float* __restrict__ maskM, const float* __restrict__ maskR,
    const float* __restrict__ word_emb, const float* __restrict__ pos_emb,
    const float* __restrict__ conv_b, float* __restrict__ out)
{
    extern __shared__ char smb[];
    float* sR = (float*)(smb + SMB_R);      // [sm][384][4]

    const int tid = threadIdx.x;
    const int lane = tid & 31, warp = tid >> 5;
    const int warp_m = warp & 3, warp_n = warp >> 2;
    const uint32_t smb_u = smem_u32(smb);

    // ---- one-time: load B (84KB), zero all 4 v tiles, gather+stage pair 0 ----
    {
        uint32_t dst = smb_u + SMB_B;
        const uint32_t* src = gBfh;
        for (int i = tid; i < KT * 8 * 32 * 4 / 4; i += 512)
            CP16(dst + i * 16, src + i * 4);
        CP_COMMIT();
    }
    for (int i = tid; i < 4 * VH_BYTES / 4; i += 512)
        ((uint32_t*)(smb + SMB_VH))[i] = 0u;
    CP_WAIT0();
    __syncthreads();
    if (blockIdx.x < SZ / 2) {
        gather_pair(smb, blockIdx.x, 0, tid, inp, pos1, pos2, word_emb, pos_emb);
        stage_pair(smb, blockIdx.x, 0, tid, maskL, maskM, maskR, conv_b);
    }

    // per-thread ldmatrix lane address part: row (lane&15), k-half block (lane>>4)*16B
    const uint32_t rowsel = (uint32_t)((lane & 15) * VROWB + ((lane >> 4) << 4));

    int it = 0;
    for (int p = blockIdx.x; p < SZ / 2; p += gridDim.x, ++it) {
        const int cur = it & 1;
        const int bs[2] = { 2 * p, 2 * p + 1 };

        __syncthreads();   // B1: pair p's v tiles + staging resident; sR free

        // ---- issue prefetch for pair p+grid (unsynced; due by B1 of next it) ----
        if (p + gridDim.x < SZ / 2) {
            gather_pair(smb, p + gridDim.x, cur ^ 1, tid, inp, pos1, pos2, word_emb, pos_emb);
            stage_pair(smb, p + gridDim.x, cur ^ 1, tid, maskL, maskM, maskR, conv_b);
        }

        // ---- GEMM mainloop on current buffers ----
        float acc[2][2][4][4];
        #pragma unroll
        for (int sm = 0; sm < 2; sm++)
            #pragma unroll
            for (int mt = 0; mt < 2; mt++)
                #pragma unroll
                for (int nt = 0; nt < 4; nt++)
                    #pragma unroll
                    for (int r = 0; r < 4; r++) acc[sm][mt][nt][r] = 0.f;

        const uint32_t vb0 = smb_u + SMB_VH + (cur * 2 + 0) * VH_BYTES + rowsel;
        const uint32_t vb1 = smb_u + SMB_VH + (cur * 2 + 1) * VH_BYTES + rowsel;
        const uint4* sB4 = (const uint4*)(smb + SMB_B);

        #pragma unroll
        for (int tap = 0; tap < 3; tap++) {
            #pragma unroll
            for (int ktl = 0; ktl < 7; ktl++) {
                const int kt = tap * 7 + ktl;
                const uint32_t roff = (uint32_t)((warp_m * 32 + tap) * VROWB + ktl * 32);
                uint32_t am[2][2][4];
                LDSM4(am[0][0][0], am[0][0][1], am[0][0][2], am[0][0][3], vb0 + roff);
                LDSM4(am[0][1][0], am[0][1][1], am[0][1][2], am[0][1][3], vb0 + roff + 16 * VROWB);
                LDSM4(am[1][0][0], am[1][0][1], am[1][0][2], am[1][0][3], vb1 + roff);
                LDSM4(am[1][1][0], am[1][1][1], am[1][1][2], am[1][1][3], vb1 + roff + 16 * VROWB);
                const uint4* bw = sB4 + kt * 256 + (warp_n * 2) * 32;
                uint4 bb0 = bw[lane];
                uint4 bb1 = bw[32 + lane];
                #pragma unroll
                for (int sm = 0; sm < 2; sm++) {
                    #pragma unroll
                    for (int mt = 0; mt < 2; mt++) {
                        MMA_F16(acc[sm][mt][0], am[sm][mt][0], am[sm][mt][1], am[sm][mt][2], am[sm][mt][3], bb0.x, bb0.y);
                        MMA_F16(acc[sm][mt][1], am[sm][mt][0], am[sm][mt][1], am[sm][mt][2], am[sm][mt][3], bb0.z, bb0.w);
                        MMA_F16(acc[sm][mt][2], am[sm][mt][0], am[sm][mt][1], am[sm][mt][2], am[sm][mt][3], bb1.x, bb1.y);
                        MMA_F16(acc[sm][mt][3], am[sm][mt][0], am[sm][mt][1], am[sm][mt][2], am[sm][mt][3], bb1.z, bb1.w);
                    }
                }
            }
        }

        // ---- epilogue (NO barrier; staging visible since B1) ----
        #pragma unroll
        for (int sm = 0; sm < 2; sm++) {
            const __half* mp = (const __half*)(smb + SMB_MASK) + (cur * 2 + sm) * 384;
            const float* cb = (const float*)(smb + SMB_CB) + (cur * 2 + sm) * 384;
            float mv[3][4];
            int srow[4];
            #pragma unroll
            for (int mt = 0; mt < 2; mt++)
                #pragma unroll
                for (int rg = 0; rg < 2; rg++) {
                    int s = warp_m * 32 + mt * 16 + (lane >> 2) + rg * 8;
                    int q = mt * 2 + rg;
                    srow[q] = s;
                    mv[0][q] = __half2float(mp[s]);
                    mv[1][q] = __half2float(mp[128 + s]);
                    mv[2][q] = __half2float(mp[256 + s]);
                }
            #pragma unroll
            for (int nt = 0; nt < 4; nt++) {
                #pragma unroll
                for (int h = 0; h < 2; h++) {
                    int o = warp_n * 32 + nt * 8 + 2 * (lane & 3) + h;
                    float C = cb[o], B0v = cb[128 + o], B2v = cb[256 + o];
                    float p0 = -3.0e38f, p1 = -3.0e38f, p2 = -3.0e38f;
                    #pragma unroll
                    for (int mt = 0; mt < 2; mt++)
                        #pragma unroll
                        for (int rg = 0; rg < 2; rg++) {
                            int q = mt * 2 + rg;
                            int s = srow[q];
                            float cv = acc[sm][mt][nt][rg * 2 + h] + C;
                            if (s == 0)   cv -= B0v;
                            if (s == 127) cv -= B2v;
                            p0 = fmaxf(p0, cv * mv[0][q]);
                            p1 = fmaxf(p1, cv * mv[1][q]);
                            p2 = fmaxf(p2, cv * mv[2][q]);
                        }
                    #pragma unroll
                    for (int off = 4; off <= 16; off <<= 1) {
                        p0 = fmaxf(p0, __shfl_xor_sync(0xffffffffu, p0, off));
                        p1 = fmaxf(p1, __shfl_xor_sync(0xffffffffu, p1, off));
                        p2 = fmaxf(p2, __shfl_xor_sync(0xffffffffu, p2, off));
                    }
                    if ((lane & 28) == 0) {
                        sR[((sm * 384 + 0 * 128 + o) << 2) + warp_m] = p0;
                        sR[((sm * 384 + 1 * 128 + o) << 2) + warp_m] = p1;
                        sR[((sm * 384 + 2 * 128 + o) << 2) + warp_m] = p2;
                    }
                }
            }
        }
        __syncthreads();   // B2: sR complete

        for (int t = tid; t < 2 * 384; t += 512) {
            int sm = t / 384, tt = t % 384;
            const float* rp = &sR[t << 2];
            float R = fmaxf(fmaxf(rp[0], rp[1]), fmaxf(rp[2], rp[3]));
            out[(size_t)bs[sm] * OUTD + tt] = tanhf(R);
        }
        // no B3: next iteration's B1 orders sR reads vs next epilogue writes
    }
}

// ============================================================================
extern "C" void kernel_launch(void* const* d_in, const int* in_sizes, int n_in,
                              void* d_out, int out_size) {
    const int*   inp       = (const int*)d_in[0];
    const int*   pos1      = (const int*)d_in[1];
    const int*   pos2      = (const int*)d_in[2];
    const int*   loc       = (const int*)d_in[3];
    const int*   loc_mark  = (const int*)d_in[4];
    const int*   subtype   = (const int*)d_in[5];
    const int*   argRole   = (const int*)d_in[6];
    const float* maskL     = (const float*)d_in[7];
    const float* maskM     = (const float*)d_in[8];
    const float* maskR     = (const float*)d_in[9];
    const float* word_emb  = (const float*)d_in[10];
    const float* pos_emb   = (const float*)d_in[11];
    const float* event_emb = (const float*)d_in[12];
    const float* role_emb  = (const float*)d_in[13];
    const float* conv_w    = (const float*)d_in[14];
    const float* conv_b    = (const float*)d_in[15];
    float* out = (float*)d_out;

    int prep_elems = KT * 16 * 32 * 2 + 3 * CCONST * DC;
    prep_kernel<<<(prep_elems + 255) / 256, 256>>>(conv_w);
    const_kernel<<<SZ / GS, 256>>>(loc, loc_mark, subtype, argRole,
                                   word_emb, event_emb, role_emb, out);
    cudaFuncSetAttribute(main_kernel, cudaFuncAttributeMaxDynamicSharedMemorySize, SMB_TOT);
    main_kernel<<<148, 512, SMB_TOT>>>(inp, pos1, pos2, maskL, maskM, maskR,
                                       word_emb, pos_emb, conv_b, out);
}

// round 14
// speedup vs baseline: 1.3357x; 1.2198x over previous
#include <cuda_runtime.h>
#include <cuda_fp16.h>
#include <math.h>
#include <stdint.h>

#define SZ     4096
#define SEN    128
#define DC     128
#define OUTD   984
#define CCONST 160
#define GS     8
#define KT     21             // k16 steps = 3 taps * 7
#define VROWB  240            // bytes per v-tile row: 120 halves (112 data + 8 pad)
#define VH_BYTES (130 * VROWB)   // 31200 per sample tile (rows x = 0..129)
#define NSTREAM 296           // 148 CTAs * 2 groups

// SMEM byte offsets
#define SMB_B    0                      // 21*8*32 uint4 = 86016
#define SMB_VH   86016                  // 4 tiles (g,buf) * 31200 = 124800 -> 210816
#define SMB_MASK 210816                 // 4 * 384 half = 3072 -> 213888
#define SMB_CB   213888                 // 4 * 384 f = 6144 -> 220032
#define SMB_R    220032                 // 2 groups * 384*2 f = 6144 -> 226176
#define SMB_TOT  226176

typedef unsigned long long u64;

__device__ __align__(16) uint32_t gBfh[KT * 8 * 32 * 4];   // fp16 B frags, uint4-grouped
__device__ __align__(16) float gW2[3 * CCONST * DC];
__device__ __align__(16) float gBase[SZ * 3 * DC];

__device__ __forceinline__ uint32_t smem_u32(const void* p) {
    uint32_t a;
    asm("{ .reg .u64 t; cvta.to.shared.u64 t, %1; cvt.u32.u64 %0, t; }" : "=r"(a) : "l"(p));
    return a;
}
#define CP16(dst_u32, src_ptr) \
    asm volatile("cp.async.cg.shared.global [%0], [%1], 16;" :: "r"(dst_u32), "l"(src_ptr) : "memory")
#define CP_COMMIT() asm volatile("cp.async.commit_group;" ::: "memory")
#define CP_WAIT0()  asm volatile("cp.async.wait_group 0;" ::: "memory")
#define BAR_G(id) asm volatile("bar.sync %0, 256;" :: "r"(id) : "memory")
#define LDSM4(r0, r1, r2, r3, addr) \
    asm volatile("ldmatrix.sync.aligned.m8n8.x4.shared.b16 {%0,%1,%2,%3}, [%4];" \
        : "=r"(r0), "=r"(r1), "=r"(r2), "=r"(r3) : "r"(addr))
#define MMA_F16(d, a0, a1, a2, a3, bx, by) \
    asm volatile("mma.sync.aligned.m16n8k16.row.col.f32.f16.f16.f32 " \
        "{%0,%1,%2,%3},{%4,%5,%6,%7},{%8,%9},{%0,%1,%2,%3};" \
        : "+f"(d[0]), "+f"(d[1]), "+f"(d[2]), "+f"(d[3]) \
        : "r"(a0), "r"(a1), "r"(a2), "r"(a3), "r"(bx), "r"(by))

// ============================================================================
// P0: fp16 B fragments grouped for LDS.128 (unchanged layout) + gW2.
// ============================================================================
__global__ void prep_kernel(const float* __restrict__ conv_w) {
    int idx = blockIdx.x * blockDim.x + threadIdx.x;
    if (idx < KT * 16 * 32 * 2) {
        int r = idx & 1, lane = (idx >> 1) & 31, nt = (idx >> 6) & 15, kt = idx >> 10;
        int o = nt * 8 + (lane >> 2);
        int j0 = kt * 16 + (lane & 3) * 2 + r * 8;
        float v0 = 0.f, v1 = 0.f;
        { int tap = j0 / 112, c = j0 % 112; if (c < 110) v0 = conv_w[o * 810 + c * 3 + tap]; }
        { int j1 = j0 + 1; int tap = j1 / 112, c = j1 % 112; if (c < 110) v1 = conv_w[o * 810 + c * 3 + tap]; }
        __half2 h = __floats2half2_rn(v0, v1);
        gBfh[((kt * 8 + (nt >> 1)) * 32 + lane) * 4 + (nt & 1) * 2 + r] = *(uint32_t*)&h;
    } else {
        int i2 = idx - KT * 16 * 32 * 2;
        if (i2 < 3 * CCONST * DC) {
            int kc = i2 / DC, o = i2 % DC;
            int k = kc / CCONST, c2 = kc % CCONST;
            gW2[i2] = conv_w[o * 810 + (110 + c2) * 3 + k];
        }
    }
}

// ============================================================================
// P1: constant-channel base + loc branch (exact fp32, unchanged).
// ============================================================================
__global__ __launch_bounds__(256) void const_kernel(
    const int* __restrict__ loc, const int* __restrict__ loc_mark,
    const int* __restrict__ subtype, const int* __restrict__ argRole,
    const float* __restrict__ word_emb, const float* __restrict__ event_emb,
    const float* __restrict__ role_emb, float* __restrict__ out)
{
    __shared__ float evrl[GS][CCONST];
    int tid = threadIdx.x;
    int b0 = blockIdx.x * GS;
    for (int i = tid; i < GS * CCONST; i += 256) {
        int g = i / CCONST, c2 = i % CCONST;
        int b = b0 + g;
        float v;
        if (c2 < 32) v = event_emb[subtype[b] * 32 + c2];
        else { int r = (c2 - 32) >> 4, q = (c2 - 32) & 15; v = role_emb[argRole[b * 8 + r] * 16 + q]; }
        evrl[g][c2] = v;
    }
    __syncthreads();
    for (int t = tid; t < 3 * DC; t += 256) {
        int o = t % DC, k = t / DC;
        float s[GS];
        #pragma unroll
        for (int g = 0; g < GS; g++) s[g] = 0.f;
        const float* w2 = &gW2[k * CCONST * DC + o];
        for (int c2 = 0; c2 < CCONST; c2++) {
            float w = w2[c2 * DC];
            #pragma unroll
            for (int g = 0; g < GS; g++) s[g] = fmaf(evrl[g][c2], w, s[g]);
        }
        #pragma unroll
        for (int g = 0; g < GS; g++) gBase[(size_t)(b0 + g) * (3 * DC) + t] = s[g];
    }
    int g = tid >> 5, lane = tid & 31;
    int b = b0 + g;
    const int* lb = &loc[b * 16];
    int mark = loc_mark[b];
    float* ob = &out[(size_t)b * OUTD + 384];
    for (int d = lane; d < 100; d += 32) {
        #pragma unroll
        for (int i = 0; i < 4; i++) ob[i * 100 + d] = tanhf(word_emb[lb[i] * 100 + d]);
        float s = 0.f;
        for (int i = 0; i < mark; i++) s += word_emb[lb[4 + i] * 100 + d];
        ob[400 + d] = tanhf(s / (float)mark);
        ob[500 + d] = tanhf(word_emb[lb[4 + mark] * 100 + d]);
    }
}

// ============================================================================
// v-tile gather for ONE sample into tile slot `slot` (256-thread group).
// ============================================================================
__device__ __forceinline__ void gather_sample(
    char* smb, int b, int slot, int tid_g,
    const int* __restrict__ inp, const int* __restrict__ pos1, const int* __restrict__ pos2,
    const float* __restrict__ word_emb, const float* __restrict__ pos_emb)
{
    char* base = smb + SMB_VH + slot * VH_BYTES;
    const int* inpb = inp + b * SEN;
    for (int idx = tid_g; idx < SEN * 25; idx += 256) {
        int s = idx / 25, q4 = idx % 25;
        float4 w4 = ((const float4*)word_emb)[(size_t)inpb[s] * 25 + q4];
        __half2 h01 = __floats2half2_rn(w4.x, w4.y);
        __half2 h23 = __floats2half2_rn(w4.z, w4.w);
        uint2 val = make_uint2(*(uint32_t*)&h01, *(uint32_t*)&h23);
        *(uint2*)(base + (s + 1) * VROWB + q4 * 8) = val;
    }
    const int* p1b = pos1 + b * SEN;
    const int* p2b = pos2 + b * SEN;
    for (int idx = tid_g; idx < SEN * 10; idx += 256) {
        int s = idx / 10, r = idx % 10;
        int row = (r < 5) ? p1b[s] : p2b[s];
        *(__half*)(base + (s + 1) * VROWB + (100 + r) * 2) =
            __float2half_rn(pos_emb[row * 5 + (r % 5)]);
    }
}

// ============================================================================
// stage masks (half 0/1 — exact) + combined bias for ONE sample, slot `slot`.
// ============================================================================
__device__ __forceinline__ void stage_sample(
    char* smb, int b, int slot, int tid_g,
    const float* __restrict__ maskL, const float* __restrict__ maskM,
    const float* __restrict__ maskR, const float* __restrict__ conv_b)
{
    __half* mdst = (__half*)(smb + SMB_MASK) + slot * 384;
    for (int i = tid_g; i < 3 * SEN; i += 256) {
        float v = (i < 128) ? maskL[b * SEN + i]
                : (i < 256) ? maskM[b * SEN + i - 128]
                            : maskR[b * SEN + i - 256];
        mdst[i] = __float2half_rn(v);
    }
    float* cb = (float*)(smb + SMB_CB) + slot * 384;
    if (tid_g < DC) {
        float b0v = gBase[(size_t)b * 384 + tid_g];
        float b1v = gBase[(size_t)b * 384 + 128 + tid_g];
        float b2v = gBase[(size_t)b * 384 + 256 + tid_g];
        cb[tid_g]       = conv_b[tid_g] + b0v + b1v + b2v;
        cb[128 + tid_g] = b0v;
        cb[256 + tid_g] = b2v;
    }
}

// ============================================================================
// Main: 148 persistent CTAs (512 thr) split into TWO independent 8-warp groups
// (each spanning all 4 SMSPs), each with its own sample stream, named barriers,
// and double-buffered tiles/staging. Shared read-only B image. One group's
// epilogue overlaps the other's HMMA mainloop (self-staggering via tensor
// contention). Per group: 1 sample/iter, warp grid 2(M) x 4(N), tile m64 x n32.
// ============================================================================
__global__ __launch_bounds__(512, 1) void main_kernel(
    const int* __restrict__ inp, const int* __restrict__ pos1, const int* __restrict__ pos2,
    const float* __restrict__ maskL, const float* __restrict__ maskM, const float* __restrict__ maskR,
    const float* __restrict__ word_emb, const float* __restrict__ pos_emb,
    const float* __restrict__ conv_b, float* __restrict__ out)
{
    extern __shared__ char smb[];

    const int tid = threadIdx.x;
    const int lane = tid & 31, warp = tid >> 5;
    const int g = (warp >> 2) & 1;          // group: warps {0-3,8-11}=0, {4-7,12-15}=1
    const int warp_m = warp >> 3;           // 0/1  (m64 per warp)
    const int warp_n = warp & 3;            // 0..3 (n32 per warp)
    const int tid_g = (warp_m * 4 + warp_n) * 32 + lane;   // 0..255 within group
    const uint32_t smb_u = smem_u32(smb);
    float* sRg = (float*)(smb + SMB_R) + g * 768;   // [3*128][2]

    // ---- one-time (all 512): load B (84KB), zero all 4 v tiles ----
    {
        uint32_t dst = smb_u + SMB_B;
        const uint32_t* src = gBfh;
        for (int i = tid; i < KT * 8 * 32 * 4 / 4; i += 512)
            CP16(dst + i * 16, src + i * 4);
        CP_COMMIT();
    }
    for (int i = tid; i < 4 * VH_BYTES / 4; i += 512)
        ((uint32_t*)(smb + SMB_VH))[i] = 0u;
    CP_WAIT0();
    __syncthreads();   // last CTA-wide barrier; groups diverge below

    // ---- per-group: gather+stage first sample into slot (g*2 + 0) ----
    const int b0 = blockIdx.x * 2 + g;
    gather_sample(smb, b0, g * 2, tid_g, inp, pos1, pos2, word_emb, pos_emb);
    stage_sample(smb, b0, g * 2, tid_g, maskL, maskM, maskR, conv_b);

    // ldmatrix lane addr part: row (lane&15), k-half block (lane>>4)*16B
    const uint32_t rowsel = (uint32_t)((lane & 15) * VROWB + ((lane >> 4) << 4));
    const int barid = g + 1;

    int itg = 0;
    for (int b = b0; b < SZ; b += NSTREAM, ++itg) {
        const int cur = itg & 1;
        const int slot = g * 2 + cur;

        BAR_G(barid);   // B1: sample b resident in slot; sRg free

        // ---- prefetch next sample (unsynced; due by next B1) ----
        if (b + NSTREAM < SZ) {
            gather_sample(smb, b + NSTREAM, g * 2 + (cur ^ 1), tid_g, inp, pos1, pos2, word_emb, pos_emb);
            stage_sample(smb, b + NSTREAM, g * 2 + (cur ^ 1), tid_g, maskL, maskM, maskR, conv_b);
        }

        // ---- GEMM mainloop: m64 x n32 per warp ----
        float acc[4][4][4];
        #pragma unroll
        for (int mt = 0; mt < 4; mt++)
            #pragma unroll
            for (int nt = 0; nt < 4; nt++)
                #pragma unroll
                for (int r = 0; r < 4; r++) acc[mt][nt][r] = 0.f;

        const uint32_t vb = smb_u + SMB_VH + slot * VH_BYTES + rowsel;
        const uint4* sB4 = (const uint4*)(smb + SMB_B);

        #pragma unroll
        for (int tap = 0; tap < 3; tap++) {
            #pragma unroll
            for (int ktl = 0; ktl < 7; ktl++) {
                const int kt = tap * 7 + ktl;
                const uint32_t roff = (uint32_t)((warp_m * 64 + tap) * VROWB + ktl * 32);
                uint32_t am[4][4];
                LDSM4(am[0][0], am[0][1], am[0][2], am[0][3], vb + roff);
                LDSM4(am[1][0], am[1][1], am[1][2], am[1][3], vb + roff + 16 * VROWB);
                LDSM4(am[2][0], am[2][1], am[2][2], am[2][3], vb + roff + 32 * VROWB);
                LDSM4(am[3][0], am[3][1], am[3][2], am[3][3], vb + roff + 48 * VROWB);
                const uint4* bw = sB4 + kt * 256 + (warp_n * 2) * 32;
                uint4 bb0 = bw[lane];
                uint4 bb1 = bw[32 + lane];
                #pragma unroll
                for (int mt = 0; mt < 4; mt++) {
                    MMA_F16(acc[mt][0], am[mt][0], am[mt][1], am[mt][2], am[mt][3], bb0.x, bb0.y);
                    MMA_F16(acc[mt][1], am[mt][0], am[mt][1], am[mt][2], am[mt][3], bb0.z, bb0.w);
                    MMA_F16(acc[mt][2], am[mt][0], am[mt][1], am[mt][2], am[mt][3], bb1.x, bb1.y);
                    MMA_F16(acc[mt][3], am[mt][0], am[mt][1], am[mt][2], am[mt][3], bb1.z, bb1.w);
                }
            }
        }

        // ---- epilogue (no barrier; staging visible since B1) ----
        {
            const __half* mp = (const __half*)(smb + SMB_MASK) + slot * 384;
            const float* cb = (const float*)(smb + SMB_CB) + slot * 384;
            float mv[3][8];
            int srow[8];
            #pragma unroll
            for (int mt = 0; mt < 4; mt++)
                #pragma unroll
                for (int rg = 0; rg < 2; rg++) {
                    int q = mt * 2 + rg;
                    int s = warp_m * 64 + mt * 16 + (lane >> 2) + rg * 8;
                    srow[q] = s;
                    mv[0][q] = __half2float(mp[s]);
                    mv[1][q] = __half2float(mp[128 + s]);
                    mv[2][q] = __half2float(mp[256 + s]);
                }
            #pragma unroll
            for (int nt = 0; nt < 4; nt++) {
                #pragma unroll
                for (int h = 0; h < 2; h++) {
                    int o = warp_n * 32 + nt * 8 + 2 * (lane & 3) + h;
                    float C = cb[o], B0v = cb[128 + o], B2v = cb[256 + o];
                    float p0 = -3.0e38f, p1 = -3.0e38f, p2 = -3.0e38f;
                    #pragma unroll
                    for (int mt = 0; mt < 4; mt++)
                        #pragma unroll
                        for (int rg = 0; rg < 2; rg++) {
                            int q = mt * 2 + rg;
                            int s = srow[q];
                            float cv = acc[mt][nt][rg * 2 + h] + C;
                            if (s == 0)   cv -= B0v;
                            if (s == 127) cv -= B2v;
                            p0 = fmaxf(p0, cv * mv[0][q]);
                            p1 = fmaxf(p1, cv * mv[1][q]);
                            p2 = fmaxf(p2, cv * mv[2][q]);
                        }
                    #pragma unroll
                    for (int off = 4; off <= 16; off <<= 1) {
                        p0 = fmaxf(p0, __shfl_xor_sync(0xffffffffu, p0, off));
                        p1 = fmaxf(p1, __shfl_xor_sync(0xffffffffu, p1, off));
                        p2 = fmaxf(p2, __shfl_xor_sync(0xffffffffu, p2, off));
                    }
                    if ((lane & 28) == 0) {
                        sRg[((0 * 128 + o) << 1) + warp_m] = p0;
                        sRg[((1 * 128 + o) << 1) + warp_m] = p1;
                        sRg[((2 * 128 + o) << 1) + warp_m] = p2;
                    }
                }
            }
        }
        BAR_G(barid);   // B2: sRg complete

        for (int t = tid_g; t < 384; t += 256) {
            const float* rp = &sRg[t << 1];
            float R = fmaxf(rp[0], rp[1]);
            out[(size_t)b * OUTD + t] = tanhf(R);
        }
        // next iteration's B1 orders sRg reads vs next epilogue writes
    }
}

// ============================================================================
extern "C" void kernel_launch(void* const* d_in, const int* in_sizes, int n_in,
                              void* d_out, int out_size) {
    const int*   inp       = (const int*)d_in[0];
    const int*   pos1      = (const int*)d_in[1];
    const int*   pos2      = (const int*)d_in[2];
    const int*   loc       = (const int*)d_in[3];
    const int*   loc_mark  = (const int*)d_in[4];
    const int*   subtype   = (const int*)d_in[5];
    const int*   argRole   = (const int*)d_in[6];
    const float* maskL     = (const float*)d_in[7];
    const float* maskM     = (const float*)d_in[8];
    const float* maskR     = (const float*)d_in[9];
    const float* word_emb  = (const float*)d_in[10];
    const float* pos_emb   = (const float*)d_in[11];
    const float* event_emb = (const float*)d_in[12];
    const float* role_emb  = (const float*)d_in[13];
    const float* conv_w    = (const float*)d_in[14];
    const float* conv_b    = (const float*)d_in[15];
    float* out = (float*)d_out;

    int prep_elems = KT * 16 * 32 * 2 + 3 * CCONST * DC;
    prep_kernel<<<(prep_elems + 255) / 256, 256>>>(conv_w);
    const_kernel<<<SZ / GS, 256>>>(loc, loc_mark, subtype, argRole,
                                   word_emb, event_emb, role_emb, out);
    cudaFuncSetAttribute(main_kernel, cudaFuncAttributeMaxDynamicSharedMemorySize, SMB_TOT);
    main_kernel<<<148, 512, SMB_TOT>>>(inp, pos1, pos2, maskL, maskM, maskR,
                                       word_emb, pos_emb, conv_b, out);
}